// round 13
// baseline (speedup 1.0000x reference)
#include <cuda_runtime.h>

// Staggered parallel transport, 8 paths, 32^4 lattice — fused, barrier-free.
//
// Layouts (row-major, metadata order):
//   d_in[0] x_re : (8, V, 3) float    d_in[1] x_im : (8, V, 3)
//   d_in[2] U_re : (4, V, 9) float    d_in[3] U_im : (4, V, 9)
//   d_out        : (2, 8, V, 3) float   (re block then im block)
// site s = ((x*32 + y)*32 + z)*32 + t
//
// Channels:
//   0: copy            1: fwd mu=0       2: fwd mu=1   3: fwd mu=2
//   4: fwd mu=3        5: bwd mu=0 (scatter)   6: bwd mu=1 (scatter)
//   7: fwd mu=0 then fwd mu=1
//
// ch7 reformulated warp-locally: out7(s) = eta1(s) U1(s) [U0(s+y) x7(s+y+x)].
// The bracket (tmp) is computed by the SAME warp that consumes it -> lives in
// 6 registers; no smem, no __syncthreads, no halo warp. The U0(s+y) rows are
// also read by the neighboring warp as its own U0(s) -> L1/L2 hits, DRAM
// traffic unchanged. Touch-once streams use evict-first hints (ldcs/stcs);
// the shared U0 stays on the caching path (__ldg).
//
// Block = 256 threads = (t:32, y:8) at fixed (x, z); warp <-> one t-line.

#define VOL (32 * 32 * 32 * 32)

__device__ __forceinline__ void mv(const float* __restrict__ Ur,
                                   const float* __restrict__ Ui,
                                   const float* vr, const float* vi,
                                   float sgn, float* yr, float* yi) {
#pragma unroll
    for (int a = 0; a < 3; a++) {
        float sr = 0.f, si = 0.f;
#pragma unroll
        for (int b = 0; b < 3; b++) {
            float ur = Ur[a * 3 + b], ui = Ui[a * 3 + b];
            sr = fmaf(ur, vr[b], sr);
            sr = fmaf(-ui, vi[b], sr);
            si = fmaf(ur, vi[b], si);
            si = fmaf(ui, vr[b], si);
        }
        yr[a] = sgn * sr;
        yi[a] = sgn * si;
    }
}

__device__ __forceinline__ void mvdag(const float* __restrict__ Ur,
                                      const float* __restrict__ Ui,
                                      const float* vr, const float* vi,
                                      float sgn, float* yr, float* yi) {
#pragma unroll
    for (int a = 0; a < 3; a++) {
        float sr = 0.f, si = 0.f;
#pragma unroll
        for (int b = 0; b < 3; b++) {
            float ur = Ur[b * 3 + a], ui = Ui[b * 3 + a];  // conj-transpose
            sr = fmaf(ur, vr[b], sr);
            sr = fmaf(ui, vi[b], sr);
            si = fmaf(ur, vi[b], si);
            si = fmaf(-ui, vr[b], si);
        }
        yr[a] = sgn * sr;
        yi[a] = sgn * si;
    }
}

// Touch-once x-vector load (evict-first)
__device__ __forceinline__ void ldv(const float* __restrict__ xr,
                                    const float* __restrict__ xi,
                                    int ch, int s, float* vr, float* vi) {
    int b = (ch * VOL + s) * 3;
#pragma unroll
    for (int c = 0; c < 3; c++) {
        vr[c] = __ldcs(xr + b + c);
        vi[c] = __ldcs(xi + b + c);
    }
}

// Touch-once U load (evict-first) — for U1/U2/U3
__device__ __forceinline__ void ldU(const float* __restrict__ Ur,
                                    const float* __restrict__ Ui,
                                    int mu, int s, float* ur, float* ui) {
    int b = (mu * VOL + s) * 9;
#pragma unroll
    for (int k = 0; k < 9; k++) {
        ur[k] = __ldcs(Ur + b + k);
        ui[k] = __ldcs(Ui + b + k);
    }
}

// Caching U load — for U0 (rows are read by two warps of the same CTA)
__device__ __forceinline__ void ldU_ca(const float* __restrict__ Ur,
                                       const float* __restrict__ Ui,
                                       int mu, int s, float* ur, float* ui) {
    int b = (mu * VOL + s) * 9;
#pragma unroll
    for (int k = 0; k < 9; k++) {
        ur[k] = __ldg(Ur + b + k);
        ui[k] = __ldg(Ui + b + k);
    }
}

__device__ __forceinline__ void stv(float* __restrict__ out, int ch, int s,
                                    const float* yr, const float* yi) {
    int br = (ch * VOL + s) * 3;
    int bi = ((8 + ch) * VOL + s) * 3;
#pragma unroll
    for (int c = 0; c < 3; c++) {
        __stcs(out + br + c, yr[c]);
        __stcs(out + bi + c, yi[c]);
    }
}

__global__ void __launch_bounds__(256, 4)
k_fused(const float* __restrict__ xr, const float* __restrict__ xi,
        const float* __restrict__ Ur, const float* __restrict__ Ui,
        float* __restrict__ out) {
    int tid = threadIdx.x;
    int t = tid & 31;
    int yl = tid >> 5;            // 0..7

    int bid = blockIdx.x;         // 0..4095
    int y0 = (bid & 3) << 3;      // {0,8,16,24}
    int z = (bid >> 2) & 31;
    int x = bid >> 7;

    int y = y0 + yl;
    int s = (x << 15) | (y << 10) | (z << 5) | t;

    int s_px = (s & ~(31 << 15)) | (((x + 1) & 31) << 15);
    int s_py = (s & ~(31 << 10)) | (((y + 1) & 31) << 10);
    int s_pz = (s & ~(31 << 5)) | (((z + 1) & 31) << 5);
    int s_pt = (s & ~31) | ((t + 1) & 31);
    // (s + y_hat) + x_hat  — x unchanged by the y shift
    int s_py_px = (s_py & ~(31 << 15)) | (((x + 1) & 31) << 15);

    float eta1 = (x & 1) ? -1.f : 1.f;            // (-1)^x
    float eta2 = ((x ^ y) & 1) ? -1.f : 1.f;      // (-1)^(x+y)
    float eta3 = ((x ^ y ^ z) & 1) ? -1.f : 1.f;  // (-1)^(x+y+z)

    float vr[3], vi[3], yr[3], yi[3];
    float tr[3], ti[3];   // ch7 intermediate, register-resident

    // ---- ch7 first hop (warp-local): tmp = U0(s+y) x7(s+y+x) ----
    {
        float Ur_[9], Ui_[9];
        ldU_ca(Ur, Ui, 0, s_py, Ur_, Ui_);       // shared with warp yl+1 -> cache
        ldv(xr, xi, 7, s_py_px, vr, vi);
        mv(Ur_, Ui_, vr, vi, 1.f, tr, ti);
    }

    // ---- ch0: identity copy ----
    ldv(xr, xi, 0, s, vr, vi);
    stv(out, 0, s, vr, vi);

    // ---- mu = 0 block: U0(s) serves ch1 and ch5 ----
    {
        float U0r[9], U0i[9];
        ldU_ca(Ur, Ui, 0, s, U0r, U0i);

        // ch1: out1(s) = U0(s) x1(s + x_hat)       (eta0 = 1)
        ldv(xr, xi, 1, s_px, vr, vi);
        mv(U0r, U0i, vr, vi, 1.f, yr, yi);
        stv(out, 1, s, yr, yi);

        // ch5 (scatter): out5(s + x_hat) = U0^dag(s) x5(s)
        ldv(xr, xi, 5, s, vr, vi);
        mvdag(U0r, U0i, vr, vi, 1.f, yr, yi);
        stv(out, 5, s_px, yr, yi);
    }

    // ---- mu = 2: ch3 ----
    {
        float U2r[9], U2i[9];
        ldU(Ur, Ui, 2, s, U2r, U2i);
        ldv(xr, xi, 3, s_pz, vr, vi);
        mv(U2r, U2i, vr, vi, eta2, yr, yi);
        stv(out, 3, s, yr, yi);
    }

    // ---- mu = 3: ch4 ----
    {
        float U3r[9], U3i[9];
        ldU(Ur, Ui, 3, s, U3r, U3i);
        ldv(xr, xi, 4, s_pt, vr, vi);
        mv(U3r, U3i, vr, vi, eta3, yr, yi);
        stv(out, 4, s, yr, yi);
    }

    // ---- mu = 1 block: U1(s) serves ch2, ch6, ch7 ----
    {
        float U1r[9], U1i[9];
        ldU(Ur, Ui, 1, s, U1r, U1i);

        // ch2: out2(s) = eta1(s) U1(s) x2(s + y_hat)
        ldv(xr, xi, 2, s_py, vr, vi);
        mv(U1r, U1i, vr, vi, eta1, yr, yi);
        stv(out, 2, s, yr, yi);

        // ch6 (scatter): out6(s + y_hat) = eta1(s) U1^dag(s) x6(s)
        ldv(xr, xi, 6, s, vr, vi);
        mvdag(U1r, U1i, vr, vi, eta1, yr, yi);
        stv(out, 6, s_py, yr, yi);

        // ch7: out7(s) = eta1(s) U1(s) tmp      [registers]
        mv(U1r, U1i, tr, ti, eta1, yr, yi);
        stv(out, 7, s, yr, yi);
    }
}

extern "C" void kernel_launch(void* const* d_in, const int* in_sizes, int n_in,
                              void* d_out, int out_size) {
    const float* xr = (const float*)d_in[0];
    const float* xi = (const float*)d_in[1];
    const float* Ur = (const float*)d_in[2];
    const float* Ui = (const float*)d_in[3];
    float* out = (float*)d_out;

    k_fused<<<4096, 256>>>(xr, xi, Ur, Ui, out);
}

// round 14
// speedup vs baseline: 1.0925x; 1.0925x over previous
#include <cuda_runtime.h>

// Staggered parallel transport, 8 paths, 32^4 lattice — fused single kernel.
// R9 structure + split producer/consumer barrier (bar.arrive / bar.sync) so
// warps never hard-sync: arrive right after producing tmp_s, sync only just
// before consuming the neighbor's row, with U2/U3/ch2/ch6 work in between.
//
// Layouts (row-major, metadata order):
//   d_in[0] x_re : (8, V, 3) float    d_in[1] x_im : (8, V, 3)
//   d_in[2] U_re : (4, V, 9) float    d_in[3] U_im : (4, V, 9)
//   d_out        : (2, 8, V, 3) float   (re block then im block)
// site s = ((x*32 + y)*32 + z)*32 + t
//
// Channels:
//   0: copy            1: fwd mu=0       2: fwd mu=1   3: fwd mu=2
//   4: fwd mu=3        5: bwd mu=0 (scatter)   6: bwd mu=1 (scatter)
//   7: fwd mu=0 then fwd mu=1  — first hop in SMEM (y-tiled block + halo)
//
// Block = 256 threads = (t:32, y:8) at fixed (x, z).

#define VOL (32 * 32 * 32 * 32)

__device__ __forceinline__ void mv(const float* __restrict__ Ur,
                                   const float* __restrict__ Ui,
                                   const float* vr, const float* vi,
                                   float sgn, float* yr, float* yi) {
#pragma unroll
    for (int a = 0; a < 3; a++) {
        float sr = 0.f, si = 0.f;
#pragma unroll
        for (int b = 0; b < 3; b++) {
            float ur = Ur[a * 3 + b], ui = Ui[a * 3 + b];
            sr = fmaf(ur, vr[b], sr);
            sr = fmaf(-ui, vi[b], sr);
            si = fmaf(ur, vi[b], si);
            si = fmaf(ui, vr[b], si);
        }
        yr[a] = sgn * sr;
        yi[a] = sgn * si;
    }
}

__device__ __forceinline__ void mvdag(const float* __restrict__ Ur,
                                      const float* __restrict__ Ui,
                                      const float* vr, const float* vi,
                                      float sgn, float* yr, float* yi) {
#pragma unroll
    for (int a = 0; a < 3; a++) {
        float sr = 0.f, si = 0.f;
#pragma unroll
        for (int b = 0; b < 3; b++) {
            float ur = Ur[b * 3 + a], ui = Ui[b * 3 + a];  // conj-transpose
            sr = fmaf(ur, vr[b], sr);
            sr = fmaf(ui, vi[b], sr);
            si = fmaf(ur, vi[b], si);
            si = fmaf(-ui, vr[b], si);
        }
        yr[a] = sgn * sr;
        yi[a] = sgn * si;
    }
}

__device__ __forceinline__ void ldv(const float* __restrict__ xr,
                                    const float* __restrict__ xi,
                                    int ch, int s, float* vr, float* vi) {
    int b = (ch * VOL + s) * 3;
#pragma unroll
    for (int c = 0; c < 3; c++) {
        vr[c] = __ldg(xr + b + c);
        vi[c] = __ldg(xi + b + c);
    }
}

__device__ __forceinline__ void ldU(const float* __restrict__ Ur,
                                    const float* __restrict__ Ui,
                                    int mu, int s, float* ur, float* ui) {
    int b = (mu * VOL + s) * 9;
#pragma unroll
    for (int k = 0; k < 9; k++) {
        ur[k] = __ldg(Ur + b + k);
        ui[k] = __ldg(Ui + b + k);
    }
}

__device__ __forceinline__ void stv(float* __restrict__ out, int ch, int s,
                                    const float* yr, const float* yi) {
    int br = (ch * VOL + s) * 3;
    int bi = ((8 + ch) * VOL + s) * 3;
#pragma unroll
    for (int c = 0; c < 3; c++) {
        out[br + c] = yr[c];
        out[bi + c] = yi[c];
    }
}

__global__ void __launch_bounds__(256, 4)
k_fused(const float* __restrict__ xr, const float* __restrict__ xi,
        const float* __restrict__ Ur, const float* __restrict__ Ui,
        float* __restrict__ out) {
    // smem tmp for ch7 first hop: [component 0..5][y-row 0..8][t]
    __shared__ float tmp_s[6][9][32];

    int tid = threadIdx.x;
    int t = tid & 31;
    int yl = tid >> 5;            // 0..7

    int bid = blockIdx.x;         // 0..4095
    int y0 = (bid & 3) << 3;      // {0,8,16,24}
    int z = (bid >> 2) & 31;
    int x = bid >> 7;

    int y = y0 + yl;
    int s = (x << 15) | (y << 10) | (z << 5) | t;

    int s_px = (s & ~(31 << 15)) | (((x + 1) & 31) << 15);
    int s_py = (s & ~(31 << 10)) | (((y + 1) & 31) << 10);
    int s_pz = (s & ~(31 << 5)) | (((z + 1) & 31) << 5);
    int s_pt = (s & ~31) | ((t + 1) & 31);

    float eta1 = (x & 1) ? -1.f : 1.f;            // (-1)^x
    float eta2 = ((x ^ y) & 1) ? -1.f : 1.f;      // (-1)^(x+y)
    float eta3 = ((x ^ y ^ z) & 1) ? -1.f : 1.f;  // (-1)^(x+y+z)

    float vr[3], vi[3], yr[3], yi[3];

    // ch0: identity copy (short live range, early MLP)
    ldv(xr, xi, 0, s, vr, vi);
    stv(out, 0, s, vr, vi);

    // ---- mu = 0 block: U0(s) serves ch1, ch5, and the ch7 first hop ----
    {
        float U0r[9], U0i[9];
        ldU(Ur, Ui, 0, s, U0r, U0i);

        // ch1: out1(s) = U0(s) x1(s + x_hat)       (eta0 = 1)
        ldv(xr, xi, 1, s_px, vr, vi);
        mv(U0r, U0i, vr, vi, 1.f, yr, yi);
        stv(out, 1, s, yr, yi);

        // ch5 (scatter): out5(s + x_hat) = U0^dag(s) x5(s)
        ldv(xr, xi, 5, s, vr, vi);
        mvdag(U0r, U0i, vr, vi, 1.f, yr, yi);
        stv(out, 5, s_px, yr, yi);

        // ch7 first hop -> smem: tmp(s) = U0(s) x7(s + x_hat)
        ldv(xr, xi, 7, s_px, vr, vi);
        mv(U0r, U0i, vr, vi, 1.f, yr, yi);
#pragma unroll
        for (int c = 0; c < 3; c++) {
            tmp_s[c][yl][t] = yr[c];
            tmp_s[3 + c][yl][t] = yi[c];
        }

        // halo row y0+8 (one warp, reuses U0 register arrays)
        if (yl == 0) {
            int yh = (y0 + 8) & 31;
            int sh = (x << 15) | (yh << 10) | (z << 5) | t;
            int sh_px = (sh & ~(31 << 15)) | (((x + 1) & 31) << 15);
            ldU(Ur, Ui, 0, sh, U0r, U0i);
            ldv(xr, xi, 7, sh_px, vr, vi);
            mv(U0r, U0i, vr, vi, 1.f, yr, yi);
#pragma unroll
            for (int c = 0; c < 3; c++) {
                tmp_s[c][8][t] = yr[c];
                tmp_s[3 + c][8][t] = yi[c];
            }
        }
    }

    // Producer side of split barrier: tmp_s rows published; don't wait.
    __threadfence_block();
    asm volatile("bar.arrive 1, 512;" ::: "memory");

    // ---- mu = 2: ch3 ----
    {
        float U2r[9], U2i[9];
        ldU(Ur, Ui, 2, s, U2r, U2i);
        ldv(xr, xi, 3, s_pz, vr, vi);
        mv(U2r, U2i, vr, vi, eta2, yr, yi);
        stv(out, 3, s, yr, yi);
    }

    // ---- mu = 3: ch4 ----
    {
        float U3r[9], U3i[9];
        ldU(Ur, Ui, 3, s, U3r, U3i);
        ldv(xr, xi, 4, s_pt, vr, vi);
        mv(U3r, U3i, vr, vi, eta3, yr, yi);
        stv(out, 4, s, yr, yi);
    }

    // ---- mu = 1 block: U1(s) serves ch2, ch6, ch7 second hop ----
    {
        float U1r[9], U1i[9];
        ldU(Ur, Ui, 1, s, U1r, U1i);

        // ch2: out2(s) = eta1(s) U1(s) x2(s + y_hat)
        ldv(xr, xi, 2, s_py, vr, vi);
        mv(U1r, U1i, vr, vi, eta1, yr, yi);
        stv(out, 2, s, yr, yi);

        // ch6 (scatter): out6(s + y_hat) = eta1(s) U1^dag(s) x6(s)
        ldv(xr, xi, 6, s, vr, vi);
        mvdag(U1r, U1i, vr, vi, eta1, yr, yi);
        stv(out, 6, s_py, yr, yi);

        // Consumer side: wait (usually already released) before reading the
        // neighbor warp's tmp row.
        asm volatile("bar.sync 1, 512;" ::: "memory");

        // ch7: out7(s) = eta1(s) U1(s) tmp(s + y_hat)   [smem]
#pragma unroll
        for (int c = 0; c < 3; c++) {
            vr[c] = tmp_s[c][yl + 1][t];
            vi[c] = tmp_s[3 + c][yl + 1][t];
        }
        mv(U1r, U1i, vr, vi, eta1, yr, yi);
        stv(out, 7, s, yr, yi);
    }
}

extern "C" void kernel_launch(void* const* d_in, const int* in_sizes, int n_in,
                              void* d_out, int out_size) {
    const float* xr = (const float*)d_in[0];
    const float* xi = (const float*)d_in[1];
    const float* Ur = (const float*)d_in[2];
    const float* Ui = (const float*)d_in[3];
    float* out = (float*)d_out;

    k_fused<<<4096, 256>>>(xr, xi, Ur, Ui, out);
}